// round 2
// baseline (speedup 1.0000x reference)
#include <cuda_runtime.h>

// Problem constants
#define BATCH 2
#define DD 160
#define HH 160
#define WW 160
#define RAD 2
#define HW (HH * WW)          // 25600
#define DHW (DD * HH * WW)    // 4096000
#define NTOT (BATCH * DHW)    // 8192000
#define INV125 (1.0f / 125.0f)

// Scratch: 5 fields (M, R, MM, RR, MR), ping-pong between passes.
__device__ float g_bufA[5u * NTOT];
__device__ float g_bufB[5u * NTOT];

// ---------------------------------------------------------------------------
// Pass 1: sliding 5-tap sum along W (contiguous dim). One block per row.
// Computes the five products on the fly from M, R.
// ---------------------------------------------------------------------------
__global__ void lncc_pass_w(const float* __restrict__ M,
                            const float* __restrict__ R) {
    const int row = blockIdx.x;        // in [0, BATCH*DD*HH)
    const int w   = threadIdx.x;       // 160 threads

    __shared__ float sm[WW + 2 * RAD];
    __shared__ float sr[WW + 2 * RAD];

    const size_t rbase = (size_t)row * WW;
    sm[w + RAD] = M[rbase + w];
    sr[w + RAD] = R[rbase + w];
    if (w < RAD) {
        sm[w] = 0.f; sr[w] = 0.f;
        sm[WW + RAD + w] = 0.f; sr[WW + RAD + w] = 0.f;
    }
    __syncthreads();

    float sM = 0.f, sR = 0.f, sMM = 0.f, sRR = 0.f, sMR = 0.f;
#pragma unroll
    for (int j = 0; j < 2 * RAD + 1; j++) {
        const float a = sm[w + j];
        const float b = sr[w + j];
        sM += a; sR += b;
        sMM = fmaf(a, a, sMM);
        sRR = fmaf(b, b, sRR);
        sMR = fmaf(a, b, sMR);
    }

    const size_t o = rbase + w;
    g_bufA[0u * NTOT + o] = sM;
    g_bufA[1u * NTOT + o] = sR;
    g_bufA[2u * NTOT + o] = sMM;
    g_bufA[3u * NTOT + o] = sRR;
    g_bufA[4u * NTOT + o] = sMR;
}

// ---------------------------------------------------------------------------
// Pass 2: sliding 5-tap sum along H. Thread = (w, h). Coalesced along w;
// tap reuse across neighboring h handled by L1/L2.
// ---------------------------------------------------------------------------
__global__ void lncc_pass_h() {
    const int w  = threadIdx.x;                          // 160
    const int h  = blockIdx.y * blockDim.y + threadIdx.y;
    const int bd = blockIdx.z;                           // b*DD + d
    const size_t base = (size_t)bd * HW;
    const size_t o = base + (size_t)h * WW + w;

#pragma unroll
    for (int f = 0; f < 5; f++) {
        const float* __restrict__ src = g_bufA + (size_t)f * NTOT + base;
        float s = 0.f;
#pragma unroll
        for (int j = -RAD; j <= RAD; j++) {
            const int hh = h + j;
            if (hh >= 0 && hh < HH)
                s += src[(size_t)hh * WW + w];
        }
        g_bufB[(size_t)f * NTOT + o] = s;
    }
}

// ---------------------------------------------------------------------------
// Pass 3: sliding 5-tap sum along D, then corr + global mean reduction.
// Thread = (w, d). blockIdx.z decodes (b, h).
// ---------------------------------------------------------------------------
__global__ void lncc_pass_d(float* __restrict__ out) {
    const int w = threadIdx.x;                            // 160
    const int d = blockIdx.y * blockDim.y + threadIdx.y;
    const int b = blockIdx.z / HH;
    const int h = blockIdx.z % HH;

    float s0 = 0.f, s1 = 0.f, s2 = 0.f, s3 = 0.f, s4 = 0.f;
#pragma unroll
    for (int j = -RAD; j <= RAD; j++) {
        const int dd = d + j;
        if (dd >= 0 && dd < DD) {
            const size_t idx = ((size_t)(b * DD + dd) * HH + h) * WW + w;
            s0 += g_bufB[0u * NTOT + idx];
            s1 += g_bufB[1u * NTOT + idx];
            s2 += g_bufB[2u * NTOT + idx];
            s3 += g_bufB[3u * NTOT + idx];
            s4 += g_bufB[4u * NTOT + idx];
        }
    }

    const float Mm  = s0 * INV125;
    const float Rm  = s1 * INV125;
    const float MMm = s2 * INV125;
    const float RRm = s3 * INV125;
    const float MRm = s4 * INV125;

    const float Mvar = sqrtf(MMm - Mm * Mm + 1e-5f);
    const float Rvar = sqrtf(RRm - Rm * Rm + 1e-5f);
    const float corr = (MRm - Mm * Rm) / (Mvar * Rvar + 1e-5f);

    // Block reduction (correct for ANY thread count): warp shuffle reduce,
    // then first warp reduces the per-warp sums, then one atomic per block.
    const int tid    = threadIdx.y * blockDim.x + threadIdx.x;  // 0..639
    const int lane   = tid & 31;
    const int warpid = tid >> 5;                                 // 0..19

    float v = corr;
#pragma unroll
    for (int off = 16; off > 0; off >>= 1)
        v += __shfl_xor_sync(0xFFFFFFFFu, v, off);

    __shared__ float warp_sums[32];
    if (lane == 0) warp_sums[warpid] = v;
    __syncthreads();

    if (warpid == 0) {
        const int nwarps = (blockDim.x * blockDim.y + 31) >> 5;  // 20
        float s = (lane < nwarps) ? warp_sums[lane] : 0.f;
#pragma unroll
        for (int off = 16; off > 0; off >>= 1)
            s += __shfl_xor_sync(0xFFFFFFFFu, s, off);
        if (lane == 0)
            atomicAdd(out, -s * (1.0f / (float)NTOT));
    }
}

__global__ void lncc_zero_out(float* out) { out[0] = 0.f; }

// ---------------------------------------------------------------------------
extern "C" void kernel_launch(void* const* d_in, const int* in_sizes, int n_in,
                              void* d_out, int out_size) {
    const float* M = (const float*)d_in[0];
    const float* R = (const float*)d_in[1];
    // d_in[2] is the box kernel (constant ones/125) — folded into INV125.
    float* out = (float*)d_out;

    lncc_zero_out<<<1, 1>>>(out);

    // Pass W: one block per (b,d,h) row.
    lncc_pass_w<<<BATCH * DD * HH, WW>>>(M, R);

    // Pass H: block (160, 4); grid (1, HH/4, BATCH*DD).
    {
        dim3 blk(WW, 4, 1);
        dim3 grd(1, HH / 4, BATCH * DD);
        lncc_pass_h<<<grd, blk>>>();
    }

    // Pass D + corr + reduce: block (160, 4); grid (1, DD/4, BATCH*HH).
    {
        dim3 blk(WW, 4, 1);
        dim3 grd(1, DD / 4, BATCH * HH);
        lncc_pass_d<<<grd, blk>>>(out);
    }
}

// round 3
// speedup vs baseline: 1.7545x; 1.7545x over previous
#include <cuda_runtime.h>

// Problem constants
#define BATCH 2
#define DD 160
#define HH 160
#define WW 160
#define RAD 2
#define NTOT (BATCH * DD * HH * WW)   // 8192000
#define INV125 (1.0f / 125.0f)

// Tile config
#define TW 32              // tile width  (W)
#define TH 8               // tile height (H)
#define DCH 40             // depth chunk per block
#define NTHR (TW * TH)     // 256
#define SROWS (TH + 2 * RAD)   // 12
#define SCOLS (TW + 2 * RAD)   // 36

__global__ void __launch_bounds__(NTHR)
lncc_fused(const float* __restrict__ M,
           const float* __restrict__ R,
           float* __restrict__ out) {
    const int tx  = threadIdx.x;            // 0..31
    const int ty  = threadIdx.y;            // 0..7
    const int tid = ty * TW + tx;           // 0..255

    const int w0 = blockIdx.x * TW;
    const int h0 = blockIdx.y * TH;
    const int bz = blockIdx.z;              // b * (DD/DCH) + chunk
    const int b  = bz / (DD / DCH);
    const int z0 = (bz % (DD / DCH)) * DCH;

    __shared__ float sm[SROWS][SCOLS];
    __shared__ float sr[SROWS][SCOLS];
    __shared__ float tmp[5][SROWS][TW];

    // Per-thread depth shift-ring: [field][age], age 4 = newest plane.
    float ring[5][5];
#pragma unroll
    for (int f = 0; f < 5; f++)
#pragma unroll
        for (int j = 0; j < 5; j++) ring[f][j] = 0.f;

    float acc = 0.f;   // sum of corr over this thread's output voxels

    // zin walks input planes z0-2 .. z0+DCH+1; output zout = zin-2 once primed.
    for (int s = 0; s < DCH + 4; s++) {
        const int zin = z0 - 2 + s;

        // Shift the ring (oldest out).
#pragma unroll
        for (int f = 0; f < 5; f++)
#pragma unroll
            for (int j = 0; j < 4; j++) ring[f][j] = ring[f][j + 1];

        if (zin >= 0 && zin < DD) {
            __syncthreads();   // prior iter's stage-2 reads of staging done

            // ---- Stage 1: load (TH+4)x(TW+4) halo tile of M, R ----
            const size_t pbase = ((size_t)(b * DD + zin)) * (HH * WW);
            for (int i = tid; i < SROWS * SCOLS; i += NTHR) {
                const int row = i / SCOLS;
                const int col = i % SCOLS;
                const int h = h0 - RAD + row;
                const int w = w0 - RAD + col;
                const bool ok = (h >= 0) & (h < HH) & (w >= 0) & (w < WW);
                const size_t g = pbase + (size_t)h * WW + w;
                sm[row][col] = ok ? M[g] : 0.f;
                sr[row][col] = ok ? R[g] : 0.f;
            }
            __syncthreads();

            // ---- Stage 2: W-filter the 5 products, all SROWS rows ----
            for (int i = tid; i < SROWS * TW; i += NTHR) {
                const int row = i >> 5;       // /TW
                const int col = i & (TW - 1);
                float aM = 0.f, aR = 0.f, aMM = 0.f, aRR = 0.f, aMR = 0.f;
#pragma unroll
                for (int k = 0; k < 2 * RAD + 1; k++) {
                    const float a = sm[row][col + k];
                    const float c = sr[row][col + k];
                    aM += a; aR += c;
                    aMM = fmaf(a, a, aMM);
                    aRR = fmaf(c, c, aRR);
                    aMR = fmaf(a, c, aMR);
                }
                tmp[0][row][col] = aM;
                tmp[1][row][col] = aR;
                tmp[2][row][col] = aMM;
                tmp[3][row][col] = aRR;
                tmp[4][row][col] = aMR;
            }
            __syncthreads();

            // ---- Stage 3: H-filter into the register ring (own voxel) ----
#pragma unroll
            for (int f = 0; f < 5; f++) {
                float sH = 0.f;
#pragma unroll
                for (int j = 0; j < 2 * RAD + 1; j++)
                    sH += tmp[f][ty + j][tx];
                ring[f][4] = sH;
            }
        } else {
            // Out-of-range plane contributes zeros (zero padding).
#pragma unroll
            for (int f = 0; f < 5; f++) ring[f][4] = 0.f;
        }

        // ---- Stage 4: emit output plane zout = zin - 2 ----
        if (zin >= z0 + 2) {
            float sums[5];
#pragma unroll
            for (int f = 0; f < 5; f++) {
                float sD = 0.f;
#pragma unroll
                for (int j = 0; j < 5; j++) sD += ring[f][j];
                sums[f] = sD;
            }
            const float Mm  = sums[0] * INV125;
            const float Rm  = sums[1] * INV125;
            const float MMm = sums[2] * INV125;
            const float RRm = sums[3] * INV125;
            const float MRm = sums[4] * INV125;

            const float Mvar = sqrtf(MMm - Mm * Mm + 1e-5f);
            const float Rvar = sqrtf(RRm - Rm * Rm + 1e-5f);
            acc += (MRm - Mm * Rm) / (Mvar * Rvar + 1e-5f);
        }
    }

    // ---- Block reduction (256 threads, power of two) + atomic ----
    __shared__ float warp_sums[NTHR / 32];
    float v = acc;
#pragma unroll
    for (int off = 16; off > 0; off >>= 1)
        v += __shfl_xor_sync(0xFFFFFFFFu, v, off);
    if ((tid & 31) == 0) warp_sums[tid >> 5] = v;
    __syncthreads();
    if (tid < 32) {
        float sWS = (tid < NTHR / 32) ? warp_sums[tid] : 0.f;
#pragma unroll
        for (int off = 4; off > 0; off >>= 1)
            sWS += __shfl_xor_sync(0xFFFFFFFFu, sWS, off);
        if (tid == 0)
            atomicAdd(out, -sWS * (1.0f / (float)NTOT));
    }
}

__global__ void lncc_zero_out(float* out) { out[0] = 0.f; }

// ---------------------------------------------------------------------------
extern "C" void kernel_launch(void* const* d_in, const int* in_sizes, int n_in,
                              void* d_out, int out_size) {
    const float* M = (const float*)d_in[0];
    const float* R = (const float*)d_in[1];
    // d_in[2] is the box kernel (ones/125) — folded into INV125.
    float* out = (float*)d_out;

    lncc_zero_out<<<1, 1>>>(out);

    dim3 blk(TW, TH, 1);
    dim3 grd(WW / TW, HH / TH, BATCH * (DD / DCH));   // (5, 20, 8) = 800 blocks
    lncc_fused<<<grd, blk>>>(M, R, out);
}

// round 4
// speedup vs baseline: 2.2922x; 1.3064x over previous
#include <cuda_runtime.h>

// Problem constants
#define BATCH 2
#define DD 160
#define HH 160
#define WW 160
#define NTOT (BATCH * DD * HH * WW)   // 8192000
#define INV125 (1.0f / 125.0f)

// Tile config
#define TW 32               // tile width (voxels)
#define TPC 16              // pair-columns (TW/2), threadIdx.x
#define TH 16               // tile height, threadIdx.y
#define DCH 20              // depth chunk per block
#define NTHR 256
#define SROWS (TH + 4)      // 20
#define SCOLS (TW + 4)      // 36
#define SCOLSP 37           // padded (odd) for bank-conflict-free rows

// Dynamic smem layout (bytes)
#define OFF_SM   0
#define OFF_SR   (SROWS * SCOLSP * 4)                       // 2960
#define OFF_TMP  (2 * SROWS * SCOLSP * 4)                   // 5920
#define OFF_HIST (OFF_TMP + 5 * SROWS * TW * 4)             // 18720
#define SMEM_TOTAL (OFF_HIST + 5 * 5 * TH * TW * 4)         // 69920

__global__ void __launch_bounds__(NTHR)
lncc_fused(const float* __restrict__ M,
           const float* __restrict__ R,
           float* __restrict__ out) {
    extern __shared__ char dynbuf[];
    float (*sm)[SCOLSP]      = (float (*)[SCOLSP])(dynbuf + OFF_SM);
    float (*sr)[SCOLSP]      = (float (*)[SCOLSP])(dynbuf + OFF_SR);
    float (*tmp)[SROWS][TW]  = (float (*)[SROWS][TW])(dynbuf + OFF_TMP);
    // hist[field][ring][row][col]
    float (*hist)[5][TH][TW] = (float (*)[5][TH][TW])(dynbuf + OFF_HIST);

    const int tx  = threadIdx.x;          // 0..15 (pair col)
    const int ty  = threadIdx.y;          // 0..15 (row)
    const int tid = ty * TPC + tx;        // 0..255
    const int x2  = 2 * tx;

    const int w0 = blockIdx.x * TW;
    const int h0 = blockIdx.y * TH;
    const int bz = blockIdx.z;            // b*(DD/DCH) + chunk
    const int b  = bz >> 3;               // DD/DCH == 8
    const int z0 = (bz & 7) * DCH;

    // Zero own ring slots (thread-private; no barrier needed).
#pragma unroll
    for (int f = 0; f < 5; f++)
#pragma unroll
        for (int j = 0; j < 5; j++)
            *(float2*)&hist[f][j][ty][x2] = make_float2(0.f, 0.f);

    float2 runs[5];
#pragma unroll
    for (int f = 0; f < 5; f++) runs[f] = make_float2(0.f, 0.f);

    float acc = 0.f;
    int rp = 0;

    for (int s = 0; s < DCH + 4; s++) {
        const int zin = z0 - 2 + s;

        if (zin >= 0 && zin < DD) {
            __syncthreads();   // prev iter's sm/sr/tmp reads complete

            // ---- Stage 1: stage M,R halo tile (20 x 36) ----
            const size_t pbase = ((size_t)(b * DD + zin)) * (HH * WW);
            for (int i = tid; i < SROWS * SCOLS; i += NTHR) {
                const int row = i / SCOLS;
                const int col = i - row * SCOLS;
                const int h = h0 - 2 + row;
                const int w = w0 - 2 + col;
                float mv = 0.f, rv = 0.f;
                if ((unsigned)h < HH && (unsigned)w < WW) {
                    const size_t g = pbase + (size_t)h * WW + w;
                    mv = M[g]; rv = R[g];
                }
                sm[row][col] = mv;
                sr[row][col] = rv;
            }
            __syncthreads();

            // ---- Stage 2: W-filter 5 products, 2 outputs per position ----
            for (int i = tid; i < SROWS * TPC; i += NTHR) {
                const int row = i >> 4;
                const int pc  = i & 15;
                const int xb  = 2 * pc;
                float m_[6], r_[6];
#pragma unroll
                for (int k = 0; k < 6; k++) { m_[k] = sm[row][xb + k]; r_[k] = sr[row][xb + k]; }
                float aM0 = 0.f, aR0 = 0.f, aMM0 = 0.f, aRR0 = 0.f, aMR0 = 0.f;
                float aM1 = 0.f, aR1 = 0.f, aMM1 = 0.f, aRR1 = 0.f, aMR1 = 0.f;
#pragma unroll
                for (int k = 0; k < 5; k++) {
                    aM0 += m_[k];  aR0 += r_[k];
                    aMM0 = fmaf(m_[k], m_[k], aMM0);
                    aRR0 = fmaf(r_[k], r_[k], aRR0);
                    aMR0 = fmaf(m_[k], r_[k], aMR0);
                    aM1 += m_[k+1]; aR1 += r_[k+1];
                    aMM1 = fmaf(m_[k+1], m_[k+1], aMM1);
                    aRR1 = fmaf(r_[k+1], r_[k+1], aRR1);
                    aMR1 = fmaf(m_[k+1], r_[k+1], aMR1);
                }
                *(float2*)&tmp[0][row][xb] = make_float2(aM0,  aM1);
                *(float2*)&tmp[1][row][xb] = make_float2(aR0,  aR1);
                *(float2*)&tmp[2][row][xb] = make_float2(aMM0, aMM1);
                *(float2*)&tmp[3][row][xb] = make_float2(aRR0, aRR1);
                *(float2*)&tmp[4][row][xb] = make_float2(aMR0, aMR1);
            }
            __syncthreads();

            // ---- Stage 3: H-filter + ring update (incremental D-sum) ----
#pragma unroll
            for (int f = 0; f < 5; f++) {
                float vx = 0.f, vy = 0.f;
#pragma unroll
                for (int j = 0; j < 5; j++) {
                    const float2 t = *(const float2*)&tmp[f][ty + j][x2];
                    vx += t.x; vy += t.y;
                }
                const float2 o = *(const float2*)&hist[f][rp][ty][x2];
                runs[f].x += vx - o.x;
                runs[f].y += vy - o.y;
                *(float2*)&hist[f][rp][ty][x2] = make_float2(vx, vy);
            }
        } else {
            // Zero plane (D zero-padding): ring update with v = 0.
#pragma unroll
            for (int f = 0; f < 5; f++) {
                const float2 o = *(const float2*)&hist[f][rp][ty][x2];
                runs[f].x -= o.x;
                runs[f].y -= o.y;
                *(float2*)&hist[f][rp][ty][x2] = make_float2(0.f, 0.f);
            }
        }

        rp = (rp == 4) ? 0 : rp + 1;

        // ---- Stage 4: emit output plane zout = zin - 2 ----
        if (s >= 4) {
#pragma unroll
            for (int c = 0; c < 2; c++) {
                const float Mm  = (c ? runs[0].y : runs[0].x) * INV125;
                const float Rm  = (c ? runs[1].y : runs[1].x) * INV125;
                const float MMm = (c ? runs[2].y : runs[2].x) * INV125;
                const float RRm = (c ? runs[3].y : runs[3].x) * INV125;
                const float MRm = (c ? runs[4].y : runs[4].x) * INV125;

                const float a  = fmaf(-Mm, Mm, MMm) + 1e-5f;
                const float bb = fmaf(-Rm, Rm, RRm) + 1e-5f;
                const float num = fmaf(-Mm, Rm, MRm);
                const float ab = a * bb;
                const float den = ab * rsqrtf(ab) + 1e-5f;  // sqrt(a)*sqrt(b)+eps
                acc += __fdividef(num, den);
            }
        }
    }

    // ---- Block reduction (256 threads) + atomic ----
    __shared__ float warp_sums[NTHR / 32];
    float v = acc;
#pragma unroll
    for (int off = 16; off > 0; off >>= 1)
        v += __shfl_xor_sync(0xFFFFFFFFu, v, off);
    if ((tid & 31) == 0) warp_sums[tid >> 5] = v;
    __syncthreads();
    if (tid < 32) {
        float sWS = (tid < NTHR / 32) ? warp_sums[tid] : 0.f;
#pragma unroll
        for (int off = 4; off > 0; off >>= 1)
            sWS += __shfl_xor_sync(0xFFFFFFFFu, sWS, off);
        if (tid == 0)
            atomicAdd(out, -sWS * (1.0f / (float)NTOT));
    }
}

__global__ void lncc_zero_out(float* out) { out[0] = 0.f; }

// ---------------------------------------------------------------------------
extern "C" void kernel_launch(void* const* d_in, const int* in_sizes, int n_in,
                              void* d_out, int out_size) {
    const float* M = (const float*)d_in[0];
    const float* R = (const float*)d_in[1];
    // d_in[2] is the box kernel (ones/125) — folded into INV125.
    float* out = (float*)d_out;

    static int attr_done = 0;  // idempotent attribute set (not a work guard)
    if (!attr_done) {
        cudaFuncSetAttribute(lncc_fused,
                             cudaFuncAttributeMaxDynamicSharedMemorySize,
                             SMEM_TOTAL);
        attr_done = 1;
    }

    lncc_zero_out<<<1, 1>>>(out);

    dim3 blk(TPC, TH, 1);                                   // (16,16) = 256
    dim3 grd(WW / TW, HH / TH, BATCH * (DD / DCH));         // (5,10,16) = 800
    lncc_fused<<<grd, blk, SMEM_TOTAL>>>(M, R, out);
}

// round 5
// speedup vs baseline: 2.9508x; 1.2873x over previous
#include <cuda_runtime.h>

// Problem constants
#define BATCH 2
#define DD 160
#define HH 160
#define WW 160
#define NTOT (BATCH * DD * HH * WW)   // 8192000
#define INV125 (1.0f / 125.0f)

// Tile config
#define TW 32               // tile width (voxels)
#define TPC 16              // pair-columns (TW/2), threadIdx.x
#define TH 16               // tile height, threadIdx.y
#define DCH 40              // depth chunk per block  -> 400 blocks, one wave
#define NCHUNK (DD / DCH)   // 4
#define NTHR 256
#define SROWS (TH + 4)      // 20
#define SCOLS (TW + 4)      // 36
#define SCOLSP 37           // odd padding: conflict-free cross-row access
#define SELEMS (SROWS * SCOLS)  // 720

// Dynamic smem layout (bytes)
#define OFF_SM   0
#define OFF_SR   (SROWS * SCOLSP * 4)                       // 2960
#define OFF_TMP  (2 * SROWS * SCOLSP * 4)                   // 5920
#define OFF_HIST (OFF_TMP + 5 * SROWS * TW * 4)             // 18720
#define SMEM_TOTAL (OFF_HIST + 5 * 5 * TH * TW * 4)         // 69920

__global__ void __launch_bounds__(NTHR)
lncc_fused(const float* __restrict__ M,
           const float* __restrict__ R,
           float* __restrict__ out) {
    extern __shared__ char dynbuf[];
    float (*sm)[SCOLSP]      = (float (*)[SCOLSP])(dynbuf + OFF_SM);
    float (*sr)[SCOLSP]      = (float (*)[SCOLSP])(dynbuf + OFF_SR);
    float (*tmp)[SROWS][TW]  = (float (*)[SROWS][TW])(dynbuf + OFF_TMP);
    float (*hist)[5][TH][TW] = (float (*)[5][TH][TW])(dynbuf + OFF_HIST);

    const int tx  = threadIdx.x;          // 0..15 (pair col)
    const int ty  = threadIdx.y;          // 0..15 (row)
    const int tid = ty * TPC + tx;        // 0..255
    const int x2  = 2 * tx;

    const int w0 = blockIdx.x * TW;
    const int h0 = blockIdx.y * TH;
    const int bz = blockIdx.z;            // b*NCHUNK + chunk
    const int b  = bz >> 2;               // NCHUNK == 4
    const int z0 = (bz & 3) * DCH;

    const size_t vol = (size_t)HH * WW;
    const float* Mb = M + (size_t)b * DD * vol;
    const float* Rb = R + (size_t)b * DD * vol;

    // ---- Precompute loop-invariant staging addresses / predicates ----
    int    ofs[3];
    bool   inb[3];
    float* smp[3];
    float* srp[3];
#pragma unroll
    for (int k = 0; k < 3; k++) {
        const int i = tid + k * NTHR;
        if (i < SELEMS) {
            const int row = i / SCOLS;
            const int col = i - row * SCOLS;
            const int h = h0 - 2 + row;
            const int w = w0 - 2 + col;
            const bool ok = ((unsigned)h < HH) & ((unsigned)w < WW);
            inb[k] = ok;
            ofs[k] = ok ? (h * WW + w) : 0;
            smp[k] = &sm[row][col];
            srp[k] = &sr[row][col];
        } else {
            inb[k] = false; ofs[k] = 0; smp[k] = nullptr; srp[k] = nullptr;
        }
    }

    // Zero own ring slots (thread-private addresses; no barrier needed).
#pragma unroll
    for (int f = 0; f < 5; f++)
#pragma unroll
        for (int j = 0; j < 5; j++)
            *(float2*)&hist[f][j][ty][x2] = make_float2(0.f, 0.f);

    float2 runs[5];
#pragma unroll
    for (int f = 0; f < 5; f++) runs[f] = make_float2(0.f, 0.f);

    float acc = 0.f;
    int rp = 0;

    // ---- Prefetch first plane (z0-2) into registers ----
    float pm[3], pr[3];
    {
        const int z = z0 - 2;
        const bool okz = (z >= 0);           // z < DD always at entry
#pragma unroll
        for (int k = 0; k < 3; k++) {
            float mv = 0.f, rv = 0.f;
            if (okz & inb[k]) {
                const size_t g = (size_t)z * vol + ofs[k];
                mv = Mb[g]; rv = Rb[g];
            }
            pm[k] = mv; pr[k] = rv;
        }
    }

    for (int s = 0; s < DCH + 4; s++) {
        // ---- Commit prefetched plane to staging ----
#pragma unroll
        for (int k = 0; k < 3; k++)
            if (smp[k]) { *smp[k] = pm[k]; *srp[k] = pr[k]; }
        __syncthreads();

        // ---- Issue next plane's loads NOW (latency hidden by stages 2+3) ----
        {
            const int z = z0 - 1 + s;
            const bool okz = ((unsigned)z < DD);
#pragma unroll
            for (int k = 0; k < 3; k++) {
                float mv = 0.f, rv = 0.f;
                if (okz & inb[k]) {
                    const size_t g = (size_t)z * vol + ofs[k];
                    mv = Mb[g]; rv = Rb[g];
                }
                pm[k] = mv; pr[k] = rv;
            }
        }

        // ---- Stage 2: W-filter 5 products, 2 outputs per position ----
        for (int i = tid; i < SROWS * TPC; i += NTHR) {
            const int row = i >> 4;
            const int pc  = i & 15;
            const int xb  = 2 * pc;
            float m_[6], r_[6];
#pragma unroll
            for (int k = 0; k < 6; k++) { m_[k] = sm[row][xb + k]; r_[k] = sr[row][xb + k]; }
            float aM0 = 0.f, aR0 = 0.f, aMM0 = 0.f, aRR0 = 0.f, aMR0 = 0.f;
            float aM1 = 0.f, aR1 = 0.f, aMM1 = 0.f, aRR1 = 0.f, aMR1 = 0.f;
#pragma unroll
            for (int k = 0; k < 5; k++) {
                aM0 += m_[k];  aR0 += r_[k];
                aMM0 = fmaf(m_[k], m_[k], aMM0);
                aRR0 = fmaf(r_[k], r_[k], aRR0);
                aMR0 = fmaf(m_[k], r_[k], aMR0);
                aM1 += m_[k+1]; aR1 += r_[k+1];
                aMM1 = fmaf(m_[k+1], m_[k+1], aMM1);
                aRR1 = fmaf(r_[k+1], r_[k+1], aRR1);
                aMR1 = fmaf(m_[k+1], r_[k+1], aMR1);
            }
            *(float2*)&tmp[0][row][xb] = make_float2(aM0,  aM1);
            *(float2*)&tmp[1][row][xb] = make_float2(aR0,  aR1);
            *(float2*)&tmp[2][row][xb] = make_float2(aMM0, aMM1);
            *(float2*)&tmp[3][row][xb] = make_float2(aRR0, aRR1);
            *(float2*)&tmp[4][row][xb] = make_float2(aMR0, aMR1);
        }
        __syncthreads();

        // ---- Stage 3: H-filter + ring update (incremental D-sum) ----
        // (For out-of-range planes the staged data was zero, so tmp is zero
        //  and the ring update correctly inserts zeros.)
#pragma unroll
        for (int f = 0; f < 5; f++) {
            float vx = 0.f, vy = 0.f;
#pragma unroll
            for (int j = 0; j < 5; j++) {
                const float2 t = *(const float2*)&tmp[f][ty + j][x2];
                vx += t.x; vy += t.y;
            }
            const float2 o = *(const float2*)&hist[f][rp][ty][x2];
            runs[f].x += vx - o.x;
            runs[f].y += vy - o.y;
            *(float2*)&hist[f][rp][ty][x2] = make_float2(vx, vy);
        }

        rp = (rp == 4) ? 0 : rp + 1;

        // ---- Stage 4: emit output plane zout = zin - 2 ----
        if (s >= 4) {
#pragma unroll
            for (int c = 0; c < 2; c++) {
                const float Mm  = (c ? runs[0].y : runs[0].x) * INV125;
                const float Rm  = (c ? runs[1].y : runs[1].x) * INV125;
                const float MMm = (c ? runs[2].y : runs[2].x) * INV125;
                const float RRm = (c ? runs[3].y : runs[3].x) * INV125;
                const float MRm = (c ? runs[4].y : runs[4].x) * INV125;

                const float a   = fmaf(-Mm, Mm, MMm) + 1e-5f;
                const float bb  = fmaf(-Rm, Rm, RRm) + 1e-5f;
                const float num = fmaf(-Mm, Rm, MRm);
                const float ab  = a * bb;
                const float den = ab * rsqrtf(ab) + 1e-5f;  // sqrt(a)*sqrt(b)+eps
                acc += __fdividef(num, den);
            }
        }
    }

    // ---- Block reduction (256 threads) + atomic ----
    __shared__ float warp_sums[NTHR / 32];
    float v = acc;
#pragma unroll
    for (int off = 16; off > 0; off >>= 1)
        v += __shfl_xor_sync(0xFFFFFFFFu, v, off);
    if ((tid & 31) == 0) warp_sums[tid >> 5] = v;
    __syncthreads();
    if (tid < 32) {
        float sWS = (tid < NTHR / 32) ? warp_sums[tid] : 0.f;
#pragma unroll
        for (int off = 4; off > 0; off >>= 1)
            sWS += __shfl_xor_sync(0xFFFFFFFFu, sWS, off);
        if (tid == 0)
            atomicAdd(out, -sWS * (1.0f / (float)NTOT));
    }
}

__global__ void lncc_zero_out(float* out) { out[0] = 0.f; }

// ---------------------------------------------------------------------------
extern "C" void kernel_launch(void* const* d_in, const int* in_sizes, int n_in,
                              void* d_out, int out_size) {
    const float* M = (const float*)d_in[0];
    const float* R = (const float*)d_in[1];
    // d_in[2] is the box kernel (ones/125) — folded into INV125.
    float* out = (float*)d_out;

    static int attr_done = 0;  // idempotent attribute set (not a work guard)
    if (!attr_done) {
        cudaFuncSetAttribute(lncc_fused,
                             cudaFuncAttributeMaxDynamicSharedMemorySize,
                             SMEM_TOTAL);
        attr_done = 1;
    }

    lncc_zero_out<<<1, 1>>>(out);

    dim3 blk(TPC, TH, 1);                                   // (16,16) = 256
    dim3 grd(WW / TW, HH / TH, BATCH * NCHUNK);             // (5,10,8) = 400
    lncc_fused<<<grd, blk, SMEM_TOTAL>>>(M, R, out);
}